// round 4
// baseline (speedup 1.0000x reference)
#include <cuda_runtime.h>

// FullAttention: B=4, L=S=2048, H=16, E=D=64, fp32, UNSCALED scores, softmax over S.
// out[b,l,h,d] = softmax_s( sum_e Q[b,l,h,e] K[b,s,h,e] ) @ V[b,s,h,d]
//
// SIMT flash attention, fp32 with packed f32x2 FMA (SASS FFMA2).
// 64x64 Q tile per CTA, 256 threads (16x16), 4x4 micro-tile per thread.
// Smem: Qs (swizzled) | KPs (K swizzled, aliased by P transposed+swizzled) | Vs (natural).

#define B_ 4
#define L_ 2048
#define S_ 2048
#define H_ 16
#define E_ 64
#define D_ 64

typedef unsigned long long u64;

__device__ __forceinline__ u64 pk2(float a, float b) {
    u64 r;
    asm("mov.b64 %0, {%1, %2};" : "=l"(r) : "f"(a), "f"(b));
    return r;
}
__device__ __forceinline__ void fma2(u64& d, u64 a, u64 b) {
    asm("fma.rn.f32x2 %0, %1, %2, %0;" : "+l"(d) : "l"(a), "l"(b));
}
__device__ __forceinline__ u64 mul2(u64 a, u64 b) {
    u64 r;
    asm("mul.rn.f32x2 %0, %1, %2;" : "=l"(r) : "l"(a), "l"(b));
    return r;
}
__device__ __forceinline__ void upk2(u64 v, float& a, float& b) {
    asm("mov.b64 {%0, %1}, %2;" : "=f"(a), "=f"(b) : "l"(v));
}

__global__ __launch_bounds__(256, 2)
void fa_fp32_kernel(const float* __restrict__ Qg_, const float* __restrict__ Kg_,
                    const float* __restrict__ Vg_, float* __restrict__ Og_) {
    __shared__ float sm[3 * 64 * 64];      // 48 KB exactly
    float* Qs  = sm;                       // [64 r][16 granules] swizzled: phys_g = g ^ (r>>2)
    float* KPs = sm + 4096;                // K tile (swizzled), later P tile (transposed+swizzled)
    float* Vs  = sm + 8192;                // [64 s][64 d] natural

    const int tid = threadIdx.x;
    const int tx  = tid & 15;              // owns score cols 4*tx..4*tx+3
    const int ty  = tid >> 4;              // owns rows 4*ty..4*ty+3
    const int q0  = blockIdx.x << 6;
    const int h   = blockIdx.y;
    const int b   = blockIdx.z;
    const int HE  = H_ * E_;               // 1024 floats row stride

    const float* Qg = Qg_ + ((size_t)(b * L_ + q0) * H_ + h) * E_;
    const float* Kg = Kg_ + ((size_t)b * S_ * H_ + h) * E_;
    const float* Vg = Vg_ + ((size_t)b * S_ * H_ + h) * E_;

    // ---- load Q tile once (swizzled) ----
    {
        const int r  = tid >> 2;
        const int g0 = tid & 3;
        const int sw = (r >> 2) & 15;
#pragma unroll
        for (int it = 0; it < 4; ++it) {
            int g = g0 + (it << 2);
            float4 v = *reinterpret_cast<const float4*>(Qg + (size_t)r * HE + (g << 2));
            *reinterpret_cast<float4*>(Qs + r * 64 + ((g ^ sw) << 2)) = v;
        }
    }

    u64   o2[4][2];                        // output accum: 4 rows x (2 d-pairs)
    float m[4], l[4];
#pragma unroll
    for (int i = 0; i < 4; ++i) {
        o2[i][0] = 0ull; o2[i][1] = 0ull;
        m[i] = -3.0e38f; l[i] = 0.0f;
    }

    for (int t = 0; t < S_ / 64; ++t) {
        __syncthreads();                   // PV reads of KPs/Vs from prev iter done
        // ---- load K (swizzled) + V (natural) tiles ----
        {
            const int r  = tid >> 2;
            const int g0 = tid & 3;
            const int sw = (r >> 2) & 15;
            const float* Kt = Kg + (size_t)(t * 64 + r) * HE;
            const float* Vt = Vg + (size_t)(t * 64 + r) * HE;
#pragma unroll
            for (int it = 0; it < 4; ++it) {
                int g = g0 + (it << 2);
                float4 kv = *reinterpret_cast<const float4*>(Kt + (g << 2));
                *reinterpret_cast<float4*>(KPs + r * 64 + ((g ^ sw) << 2)) = kv;
                float4 vv = *reinterpret_cast<const float4*>(Vt + (g << 2));
                *reinterpret_cast<float4*>(Vs + r * 64 + (g << 2)) = vv;
            }
        }
        __syncthreads();

        // ---- S = Q K^T : packed over e (reduction dim) ----
        u64 acc[4][4];
#pragma unroll
        for (int i = 0; i < 4; ++i)
#pragma unroll
            for (int j = 0; j < 4; ++j) acc[i][j] = 0ull;

#pragma unroll 4
        for (int e4 = 0; e4 < 16; ++e4) {
            float4 q4[4], k4[4];
#pragma unroll
            for (int i = 0; i < 4; ++i)
                q4[i] = *reinterpret_cast<const float4*>(Qs + (4 * ty + i) * 64 + (((e4 ^ ty) & 15) << 2));
#pragma unroll
            for (int j = 0; j < 4; ++j)
                k4[j] = *reinterpret_cast<const float4*>(KPs + (4 * tx + j) * 64 + (((e4 ^ tx) & 15) << 2));
            u64 klo[4], khi[4];
#pragma unroll
            for (int j = 0; j < 4; ++j) { klo[j] = pk2(k4[j].x, k4[j].y); khi[j] = pk2(k4[j].z, k4[j].w); }
#pragma unroll
            for (int i = 0; i < 4; ++i) {
                u64 qlo = pk2(q4[i].x, q4[i].y);
                u64 qhi = pk2(q4[i].z, q4[i].w);
#pragma unroll
                for (int j = 0; j < 4; ++j) {
                    fma2(acc[i][j], qlo, klo[j]);
                    fma2(acc[i][j], qhi, khi[j]);
                }
            }
        }

        // ---- online softmax (row reductions across tx via half-warp shfl) ----
        float p[4][4];
#pragma unroll
        for (int i = 0; i < 4; ++i) {
            float sj[4];
#pragma unroll
            for (int j = 0; j < 4; ++j) {
                float a0, a1;
                upk2(acc[i][j], a0, a1);
                sj[j] = a0 + a1;
            }
            float tmax = fmaxf(fmaxf(sj[0], sj[1]), fmaxf(sj[2], sj[3]));
#pragma unroll
            for (int k = 1; k < 16; k <<= 1)
                tmax = fmaxf(tmax, __shfl_xor_sync(0xffffffffu, tmax, k));
            float mn   = fmaxf(m[i], tmax);
            float corr = __expf(m[i] - mn);
            m[i] = mn;
            float rs = 0.0f;
#pragma unroll
            for (int j = 0; j < 4; ++j) {
                p[i][j] = __expf(sj[j] - mn);
                rs += p[i][j];
            }
#pragma unroll
            for (int k = 1; k < 16; k <<= 1)
                rs += __shfl_xor_sync(0xffffffffu, rs, k);
            l[i] = l[i] * corr + rs;
            u64 c2 = pk2(corr, corr);
            o2[i][0] = mul2(o2[i][0], c2);
            o2[i][1] = mul2(o2[i][1], c2);
        }

        __syncthreads();                   // all QK reads of KPs done; safe to overwrite with P
        // ---- store P transposed+swizzled: row = key index c, granule ty holds rows 4ty..4ty+3
        {
            const int sw = (ty ^ tx) & 15;
#pragma unroll
            for (int j = 0; j < 4; ++j) {
                float4 pv = make_float4(p[0][j], p[1][j], p[2][j], p[3][j]);
                *reinterpret_cast<float4*>(KPs + (4 * tx + j) * 64 + (sw << 2)) = pv;
            }
        }
        __syncthreads();

        // ---- O += P V : packed over d (output dim) ----
#pragma unroll 8
        for (int s = 0; s < 64; ++s) {
            float4 p4 = *reinterpret_cast<const float4*>(KPs + s * 64 + (((ty ^ (s >> 2)) & 15) << 2));
            float4 v4 = *reinterpret_cast<const float4*>(Vs + s * 64 + (tx << 2));
            u64 vlo = pk2(v4.x, v4.y);
            u64 vhi = pk2(v4.z, v4.w);
            u64 pp;
            pp = pk2(p4.x, p4.x); fma2(o2[0][0], pp, vlo); fma2(o2[0][1], pp, vhi);
            pp = pk2(p4.y, p4.y); fma2(o2[1][0], pp, vlo); fma2(o2[1][1], pp, vhi);
            pp = pk2(p4.z, p4.z); fma2(o2[2][0], pp, vlo); fma2(o2[2][1], pp, vhi);
            pp = pk2(p4.w, p4.w); fma2(o2[3][0], pp, vlo); fma2(o2[3][1], pp, vhi);
        }
    }

    // ---- epilogue: normalize and store [B,L,H,D], coalesced float4 ----
#pragma unroll
    for (int i = 0; i < 4; ++i) {
        float inv = 1.0f / l[i];
        float a0, a1, a2, a3;
        upk2(o2[i][0], a0, a1);
        upk2(o2[i][1], a2, a3);
        float4 o = make_float4(a0 * inv, a1 * inv, a2 * inv, a3 * inv);
        float* Op = Og_ + ((size_t)(b * L_ + q0 + 4 * ty + i) * H_ + h) * D_ + (tx << 2);
        *reinterpret_cast<float4*>(Op) = o;
    }
}

extern "C" void kernel_launch(void* const* d_in, const int* in_sizes, int n_in,
                              void* d_out, int out_size) {
    (void)in_sizes; (void)n_in; (void)out_size;
    const float* q = (const float*)d_in[0];
    const float* k = (const float*)d_in[1];
    const float* v = (const float*)d_in[2];
    float* o = (float*)d_out;
    dim3 grid(L_ / 64, H_, B_);            // 32 x 16 x 4 = 2048 CTAs
    fa_fp32_kernel<<<grid, 256>>>(q, k, v, o);
}